// round 12
// baseline (speedup 1.0000x reference)
#include <cuda_runtime.h>
#include <cuda_fp16.h>
#include <cstdint>

// ---------------------------------------------------------------------------
// BaseAttention fused — HMMA m16n8k16, warp-specialized pipeline (fixed).
//   producers: 512 thr (16 warps), strip-decoupled 3-layer MLP -> xr, qp
//   consumer : 128 thr (4 warps), attention tail of the PREVIOUS tile
// Handshake: named bar 9 (B_READY: prod arrive / cons sync),
//            named bar 10 (B_FREE: cons arrive / prod sync before xr store).
// qp/msp/mask double-buffered; xr single-buffered (gated by B_FREE).
// R11 NaN fix: q_cs/p_cs were sized 512B but need 2048B (overran into W1).
// Also: mask values hoisted into registers before the cross-phase barrier.
// ---------------------------------------------------------------------------

#define kBatch   32768
#define kTiles   (kBatch / 4)     // 8192
#define kGrid    148
#define kProd    512
#define kThreads 640

// smem byte offsets
#define OFF_FS      0                // [128][16] f32 raw att (producer-private) 8192
#define OFF_BIAS    8192             // b1,b2,b3 f32                             1536
#define OFF_MSPDB   9728             // [2][8] f32 strip mask sums                 64
#define OFF_MASKDB  9792             // [2][128] f32 masks                       1024
#define OFF_QPDB    10816            // [2][8][128] f32 strip col sums           8192
#define OFF_QCS     19008            // [4][128] f32 consumer query              2048
#define OFF_PCS     21056            // [4][128] f32 consumer p                  2048
#define OFF_WCS     23104            // [128] f32 softmax w                       512
#define OFF_W1T     23616            // [128][24] f16 (k-pad)                    6144
#define OFF_A       29760            // [128][136] f16 activations              34816
#define OFF_W2T     64576            // [128][136] f16                          34816
#define OFF_W3T     99392            // [128][136] f16                          34816
#define OFF_XR      134208           // [128][129] f32                          66048
#define SMEM_BYTES  200256           // < 232448 opt-in limit

#define A_STRIDE  272                // bytes per A/W row (136 halves)
#define W1_STRIDE 48                 // bytes per W1 row (24 halves)

__device__ __half g_W1h[128 * 24];
__device__ __half g_W2h[128 * 136];
__device__ __half g_W3h[128 * 136];
__device__ float  g_MT[128 * 128];   // MT[j*128+t] = sum_k Ur[k,t]*Uq[k,j]

__device__ __forceinline__ uint32_t smem_u32(const void* p) {
    uint32_t a;
    asm("{ .reg .u64 t; cvta.to.shared.u64 t, %1; cvt.u32.u64 %0, t; }" : "=r"(a) : "l"(p));
    return a;
}

#define BAR64(S)         asm volatile("bar.sync %0, 64;"   :: "r"(1 + (S)) : "memory")
#define BAR_SYNC(ID,N)   asm volatile("bar.sync %0, %1;"   :: "r"(ID), "r"(N) : "memory")
#define BAR_ARRIVE(ID,N) asm volatile("bar.arrive %0, %1;" :: "r"(ID), "r"(N) : "memory")
#define B_READY 9
#define B_FREE  10
#define B_CONS  11

#define LDSM_X4(R0,R1,R2,R3,ADDR) \
    asm volatile("ldmatrix.sync.aligned.m8n8.x4.shared.b16 {%0,%1,%2,%3}, [%4];" \
                 : "=r"(R0), "=r"(R1), "=r"(R2), "=r"(R3) : "r"(ADDR))

#define MMA_16816(D_, A0,A1,A2,A3, B0,B1) \
    asm volatile("mma.sync.aligned.m16n8k16.row.col.f32.f16.f16.f32 " \
                 "{%0,%1,%2,%3}, {%4,%5,%6,%7}, {%8,%9}, {%0,%1,%2,%3};" \
                 : "+f"((D_)[0]), "+f"((D_)[1]), "+f"((D_)[2]), "+f"((D_)[3]) \
                 : "r"(A0), "r"(A1), "r"(A2), "r"(A3), "r"(B0), "r"(B1))

// ---- prep kernels ----
__global__ void pack_weights(const float* __restrict__ W1,
                             const float* __restrict__ W2,
                             const float* __restrict__ W3) {
    int i = blockIdx.x * 256 + threadIdx.x;      // 68*256 = 17408
    if (i < 128 * 136) {
        int n = i / 136, c = i % 136;
        g_W2h[i] = __float2half((c < 128) ? W2[n * 128 + c] : 0.f);
        g_W3h[i] = __float2half((c < 128) ? W3[n * 128 + c] : 0.f);
    }
    if (i < 128 * 24) {
        int n = i / 24, c = i % 24;
        g_W1h[i] = __float2half((c < 15) ? W1[n * 15 + c] : 0.f);
    }
}

__global__ void precompute_MT(const float* __restrict__ Uq, const float* __restrict__ Ur) {
    int j = blockIdx.x, t = threadIdx.x;
    float acc = 0.f;
    #pragma unroll 8
    for (int k = 0; k < 128; ++k)
        acc += Ur[k * 128 + t] * Uq[k * 128 + j];
    g_MT[j * 128 + t] = acc;
}

// K-loop GEMM: D[16 rows][64 cols] += A_strip @ W_half^T
template<int NK, int BSTRIDE>
__device__ __forceinline__ void gemm_strip(uint32_t aAddr, uint32_t bAddr, float (&d)[8][4]) {
    #pragma unroll
    for (int k = 0; k < NK; ++k) {
        uint32_t a0, a1, a2, a3;
        LDSM_X4(a0, a1, a2, a3, aAddr + k * 32);
        #pragma unroll
        for (int nt2 = 0; nt2 < 4; ++nt2) {
            uint32_t q0, q1, q2, q3;
            LDSM_X4(q0, q1, q2, q3, bAddr + nt2 * 16 * BSTRIDE + k * 32);
            MMA_16816(d[2 * nt2],     a0, a1, a2, a3, q0, q1);
            MMA_16816(d[2 * nt2 + 1], a0, a1, a2, a3, q2, q3);
        }
    }
}

extern __shared__ char smem[];

__global__ __launch_bounds__(kThreads, 1) void fused_attn_hmma(
    const float* __restrict__ obs,
    const float* __restrict__ b1, const float* __restrict__ b2, const float* __restrict__ b3,
    float* __restrict__ out)
{
    const uint32_t sb = smem_u32(smem);
    const int tid  = threadIdx.x;

    // stage weights + biases (all 640 threads)
    {
        const uint4* s1 = (const uint4*)g_W1h;
        const uint4* s2 = (const uint4*)g_W2h;
        const uint4* s3 = (const uint4*)g_W3h;
        for (int i = tid; i < 384;  i += kThreads) *(uint4*)(smem + OFF_W1T + i * 16) = s1[i];
        for (int i = tid; i < 2176; i += kThreads) *(uint4*)(smem + OFF_W2T + i * 16) = s2[i];
        for (int i = tid; i < 2176; i += kThreads) *(uint4*)(smem + OFF_W3T + i * 16) = s3[i];
        if (tid < 128) {
            ((float*)(smem + OFF_BIAS))[tid]       = b1[tid];
            ((float*)(smem + OFF_BIAS))[128 + tid] = b2[tid];
            ((float*)(smem + OFF_BIAS))[256 + tid] = b3[tid];
        }
    }
    __syncthreads();

    float* fs      = (float*)(smem + OFF_FS);
    float* xr      = (float*)(smem + OFF_XR);
    const float* bias = (const float*)(smem + OFF_BIAS);
    float* msp_db  = (float*)(smem + OFF_MSPDB);    // [2][8]
    float* mask_db = (float*)(smem + OFF_MASKDB);   // [2][128]
    float* qp_db   = (float*)(smem + OFF_QPDB);     // [2][8][128]

    if (tid < kProd) {
        // =================== PRODUCER (512 threads, 16 warps) ===================
        const int lane = tid & 31;
        const int wid  = tid >> 5;
        const int s    = wid >> 1;               // strip 0..7
        const int nh   = wid & 1;                // N-half 0..1
        const int r0   = s * 16;
        const int nbase = nh * 64;
        const int pairtid = tid & 63;

        const uint32_t aAddr = sb + OFF_A + (uint32_t)(r0 + (lane & 15)) * A_STRIDE + (uint32_t)(lane >> 4) * 16;
        const uint32_t brow  = (uint32_t)((lane & 7) + ((lane >> 4) << 3));
        const uint32_t koff  = (uint32_t)(((lane >> 3) & 1) * 16);
        const uint32_t bW1   = sb + OFF_W1T + (nbase + brow) * W1_STRIDE + koff;
        const uint32_t bW2   = sb + OFF_W2T + (nbase + brow) * A_STRIDE + koff;
        const uint32_t bW3   = sb + OFF_W3T + (nbase + brow) * A_STRIDE + koff;

        const int rA = r0 + (lane >> 2);          // rows rA and rA+8
        const int cn = (lane & 3) * 2;            // col offset within n-tile

        const int fs_r  = r0 + (pairtid >> 2);    // obs staging row
        const int fs_c4 = pairtid & 3;

        float4 pf_att;
        {
            const float4* o4 = (const float4*)(obs + (size_t)blockIdx.x * 4 * 576);
            pf_att = o4[(fs_r >> 5) * 144 + 8 + (fs_r & 31) * 4 + fs_c4];
        }

        int buf = 0;
        for (int tile = blockIdx.x; tile < kTiles; tile += kGrid, buf ^= 1) {
            // ---- commit prefetched att (strip-local) ----
            ((float4*)fs)[fs_r * 4 + fs_c4] = pf_att;
            BAR64(s);

            // ---- A1: feats fp16 + mask/msum into double buffers ----
            #pragma unroll
            for (int k2 = 0; k2 < 2; ++k2) {
                const int i = pairtid + 64 * k2;
                const int r = r0 + (i >> 3), cp = i & 7;
                float2 v = *(const float2*)(fs + r * 16 + 2 * cp);
                if (cp == 7) v.y = 0.f;           // col 15 = mask -> 0
                __half2 h = __floats2half2_rn(v.x, v.y);
                *(uint32_t*)(smem + OFF_A + r * A_STRIDE + cp * 4) = *(uint32_t*)&h;
            }
            if (pairtid < 16)
                mask_db[buf * 128 + r0 + pairtid] = fs[(r0 + pairtid) * 16 + 15];
            if (pairtid == 0) {
                float ssum = 0.f;
                #pragma unroll
                for (int rr = 0; rr < 16; ++rr) ssum += fs[(r0 + rr) * 16 + 15];
                msp_db[buf * 8 + s] = ssum;
            }
            BAR64(s);

            float d[8][4];

            // ---- layer 1 (K=16) ----
            #pragma unroll
            for (int nt = 0; nt < 8; ++nt)
                { d[nt][0] = d[nt][1] = d[nt][2] = d[nt][3] = 0.f; }
            gemm_strip<1, W1_STRIDE>(aAddr, bW1, d);
            BAR64(s);
            #pragma unroll
            for (int nt = 0; nt < 8; ++nt) {      // epi: relu(+b1) -> A fp16
                const int n = nbase + nt * 8 + cn;
                __half2 h0 = __floats2half2_rn(fmaxf(d[nt][0] + bias[n],     0.f),
                                               fmaxf(d[nt][1] + bias[n + 1], 0.f));
                __half2 h1 = __floats2half2_rn(fmaxf(d[nt][2] + bias[n],     0.f),
                                               fmaxf(d[nt][3] + bias[n + 1], 0.f));
                *(uint32_t*)(smem + OFF_A + rA * A_STRIDE + n * 2)       = *(uint32_t*)&h0;
                *(uint32_t*)(smem + OFF_A + (rA + 8) * A_STRIDE + n * 2) = *(uint32_t*)&h1;
            }
            BAR64(s);

            // ---- layer 2 (K=128) ----
            #pragma unroll
            for (int nt = 0; nt < 8; ++nt)
                { d[nt][0] = d[nt][1] = d[nt][2] = d[nt][3] = 0.f; }
            gemm_strip<8, A_STRIDE>(aAddr, bW2, d);
            BAR64(s);
            #pragma unroll
            for (int nt = 0; nt < 8; ++nt) {      // epi: relu(+b2) -> A fp16
                const int n = nbase + nt * 8 + cn;
                __half2 h0 = __floats2half2_rn(fmaxf(d[nt][0] + bias[128 + n],     0.f),
                                               fmaxf(d[nt][1] + bias[128 + n + 1], 0.f));
                __half2 h1 = __floats2half2_rn(fmaxf(d[nt][2] + bias[128 + n],     0.f),
                                               fmaxf(d[nt][3] + bias[128 + n + 1], 0.f));
                *(uint32_t*)(smem + OFF_A + rA * A_STRIDE + n * 2)       = *(uint32_t*)&h0;
                *(uint32_t*)(smem + OFF_A + (rA + 8) * A_STRIDE + n * 2) = *(uint32_t*)&h1;
            }
            BAR64(s);

            // ---- layer 3 (K=128) compute ----
            #pragma unroll
            for (int nt = 0; nt < 8; ++nt)
                { d[nt][0] = d[nt][1] = d[nt][2] = d[nt][3] = 0.f; }
            gemm_strip<8, A_STRIDE>(aAddr, bW3, d);

            // masks into registers BEFORE any cross-phase barrier (fs is stable
            // here: partner warp cannot recommit fs until we pass B_FREE too)
            const float mkA = fs[rA * 16 + 15];
            const float mkB = fs[(rA + 8) * 16 + 15];

            // ---- prefetch next tile's obs (before blocking on consumer) ----
            {
                const int ntile = tile + kGrid;
                if (ntile < kTiles) {
                    const float4* o4 = (const float4*)(obs + (size_t)ntile * 4 * 576);
                    pf_att = o4[(fs_r >> 5) * 144 + 8 + (fs_r & 31) * 4 + fs_c4];
                }
            }

            // ---- wait for consumer to release xr, then store xr + qp ----
            BAR_SYNC(B_FREE, kThreads);
            {
                float qa[8], qb[8];
                #pragma unroll
                for (int nt = 0; nt < 8; ++nt) {
                    const int n = nbase + nt * 8 + cn;
                    const float xA0 = (d[nt][0] + bias[256 + n])     * mkA;
                    const float xA1 = (d[nt][1] + bias[256 + n + 1]) * mkA;
                    const float xB0 = (d[nt][2] + bias[256 + n])     * mkB;
                    const float xB1 = (d[nt][3] + bias[256 + n + 1]) * mkB;
                    xr[rA * 129 + n]           = xA0;
                    xr[rA * 129 + n + 1]       = xA1;
                    xr[(rA + 8) * 129 + n]     = xB0;
                    xr[(rA + 8) * 129 + n + 1] = xB1;
                    qa[nt] = xA0 + xB0;
                    qb[nt] = xA1 + xB1;
                }
                #pragma unroll
                for (int off = 4; off < 32; off <<= 1) {
                    #pragma unroll
                    for (int nt = 0; nt < 8; ++nt) {
                        qa[nt] += __shfl_xor_sync(0xffffffffu, qa[nt], off);
                        qb[nt] += __shfl_xor_sync(0xffffffffu, qb[nt], off);
                    }
                }
                if ((lane >> 2) == 0) {           // lanes 0..3 write strip col sums
                    #pragma unroll
                    for (int nt = 0; nt < 8; ++nt) {
                        const int n = nbase + nt * 8 + cn;
                        qp_db[buf * 1024 + s * 128 + n]     = qa[nt];
                        qp_db[buf * 1024 + s * 128 + n + 1] = qb[nt];
                    }
                }
            }
            BAR_ARRIVE(B_READY, kThreads);
        }
    } else {
        // =================== CONSUMER (128 threads, 4 warps) ===================
        const int tid2 = tid - kProd;             // 0..127
        const int cw   = tid2 >> 5;               // consumer warp 0..3 = batch row
        float* q_cs = (float*)(smem + OFF_QCS);
        float* p_cs = (float*)(smem + OFF_PCS);
        float* w_cs = (float*)(smem + OFF_WCS);

        BAR_ARRIVE(B_FREE, kThreads);             // prime the pipeline

        int buf = 0;
        for (int tile = blockIdx.x; tile < kTiles; tile += kGrid, buf ^= 1) {
            const int b0 = tile * 4;

            // aux passthrough (overlaps producer GEMM; independent of xr)
            if (tid2 < 64) {
                const float4* o4 = (const float4*)(obs + (size_t)b0 * 576);
                const int lb = tid2 >> 4, j = tid2 & 15;
                float4 v = (j < 8) ? o4[lb * 144 + j] : o4[lb * 144 + 136 + (j - 8)];
                ((float4*)(out + (size_t)b0 * 192))[lb * 48 + j] = v;
            }

            BAR_SYNC(B_READY, kThreads);          // xr, qp, msp, mask ready

            const int dd = tid2;                  // 0..127 (feature dim)
            // ---- query ----
            #pragma unroll
            for (int lb = 0; lb < 4; ++lb) {
                const float qs = qp_db[buf * 1024 + (2 * lb) * 128 + dd]
                               + qp_db[buf * 1024 + (2 * lb + 1) * 128 + dd];
                q_cs[lb * 128 + dd] = qs / (msp_db[buf * 8 + 2 * lb] + msp_db[buf * 8 + 2 * lb + 1] + 1e-5f);
            }
            BAR_SYNC(B_CONS, 128);

            // ---- p = MT q (g_MT hot in L2) ----
            {
                float p0 = 0.f, p1 = 0.f, p2 = 0.f, p3 = 0.f;
                #pragma unroll 8
                for (int j = 0; j < 128; ++j) {
                    const float m = g_MT[j * 128 + dd];
                    p0 += m * q_cs[j];
                    p1 += m * q_cs[128 + j];
                    p2 += m * q_cs[256 + j];
                    p3 += m * q_cs[384 + j];
                }
                p_cs[dd]       = p0;
                p_cs[128 + dd] = p1;
                p_cs[256 + dd] = p2;
                p_cs[384 + dd] = p3;
            }
            BAR_SYNC(B_CONS, 128);

            // ---- logits + softmax: warp cw owns batch row cw, lane = object ----
            {
                const int row = tid2;             // object row 0..127, batch = row>>5 = cw
                float ls = 0.f;
                #pragma unroll 8
                for (int k = 0; k < 128; ++k)
                    ls += p_cs[cw * 128 + k] * xr[row * 129 + k];
                ls += (1.f - mask_db[buf * 128 + row]) * -1e9f;
                float mx = ls;
                #pragma unroll
                for (int sh = 16; sh > 0; sh >>= 1) mx = fmaxf(mx, __shfl_xor_sync(0xffffffffu, mx, sh));
                const float e = __expf(ls - mx);
                float ssum = e;
                #pragma unroll
                for (int sh = 16; sh > 0; sh >>= 1) ssum += __shfl_xor_sync(0xffffffffu, ssum, sh);
                w_cs[row] = e / ssum;
            }
            BAR_SYNC(B_CONS, 128);

            // ---- out_att ----
            #pragma unroll
            for (int lb = 0; lb < 4; ++lb) {
                float acc = 0.f;
                #pragma unroll 8
                for (int o = 0; o < 32; ++o)
                    acc += w_cs[lb * 32 + o] * xr[(lb * 32 + o) * 129 + dd];
                out[(size_t)(b0 + lb) * 192 + 64 + dd] = acc;
            }

            BAR_ARRIVE(B_FREE, kThreads);         // release xr for next tile
        }
    }
}

extern "C" void kernel_launch(void* const* d_in, const int* in_sizes, int n_in,
                              void* d_out, int out_size) {
    const float* obs = (const float*)d_in[0];
    const float* W1  = (const float*)d_in[1];
    const float* b1  = (const float*)d_in[2];
    const float* W2  = (const float*)d_in[3];
    const float* b2  = (const float*)d_in[4];
    const float* W3  = (const float*)d_in[5];
    const float* b3  = (const float*)d_in[6];
    const float* Uq  = (const float*)d_in[7];
    const float* Ur  = (const float*)d_in[8];
    float* out = (float*)d_out;

    cudaFuncSetAttribute(fused_attn_hmma,
                         cudaFuncAttributeMaxDynamicSharedMemorySize, (int)SMEM_BYTES);

    pack_weights<<<68, 256>>>(W1, W2, W3);
    precompute_MT<<<128, 128>>>(Uq, Ur);
    fused_attn_hmma<<<kGrid, kThreads, SMEM_BYTES>>>(obs, b1, b2, b3, out);
}

// round 13
// speedup vs baseline: 1.1193x; 1.1193x over previous
#include <cuda_runtime.h>
#include <cuda_fp16.h>
#include <cstdint>

// ---------------------------------------------------------------------------
// BaseAttention fused — HMMA m16n8k16, register-resident layer chaining.
// 8 producer warps: warp s owns rows [16s,16s+16) x ALL 128 cols.
//   L1 (K=16) from smem A1; L2/L3 A-operands are the previous layer's
//   D-fragments converted in registers (D-layout == A-layout for n128).
//   No inter-layer smem traffic, no inter-layer barriers.
// 4 consumer warps: attention tail of the previous tile (incl. query).
// ---------------------------------------------------------------------------

#define kBatch   32768
#define kTiles   (kBatch / 4)     // 8192
#define kGrid    148
#define kProd    256
#define kThreads 384

// smem byte offsets
#define OFF_FS      0                // [128][16] f32 raw att (producer-private) 8192
#define OFF_BIAS    8192             // b1,b2,b3 f32                             1536
#define OFF_MSPDB   9728             // [2][8] f32 strip mask sums                 64
#define OFF_MASKDB  9792             // [2][128] f32 masks                       1024
#define OFF_QCS     10816            // [4][128] f32 consumer query              2048
#define OFF_PCS     12864            // [4][128] f32 consumer p                  2048
#define OFF_WCS     14912            // [128] f32 softmax w                       512
#define OFF_W1T     15424            // [128][24] f16 (k-pad 15->16)             6144
#define OFF_A       21568            // [128][24] f16 A1 tile (stride 48B)       6144
#define OFF_W2T     27712            // [128][136] f16                          34816
#define OFF_W3T     62528            // [128][136] f16                          34816
#define OFF_XR      97344            // [128][130] f32                          66560
#define SMEM_BYTES  163904           // < 232448 opt-in limit

#define W_STRIDE  272                // bytes per W2/W3 row (136 halves)
#define W1_STRIDE 48                 // bytes per W1/A1 row (24 halves)

__device__ __half g_W1h[128 * 24];
__device__ __half g_W2h[128 * 136];
__device__ __half g_W3h[128 * 136];
__device__ float  g_MT[128 * 128];   // MT[j*128+t] = sum_k Ur[k,t]*Uq[k,j]

__device__ __forceinline__ uint32_t smem_u32(const void* p) {
    uint32_t a;
    asm("{ .reg .u64 t; cvta.to.shared.u64 t, %1; cvt.u32.u64 %0, t; }" : "=r"(a) : "l"(p));
    return a;
}

#define BAR_SYNC(ID,N)   asm volatile("bar.sync %0, %1;"   :: "r"(ID), "r"(N) : "memory")
#define BAR_ARRIVE(ID,N) asm volatile("bar.arrive %0, %1;" :: "r"(ID), "r"(N) : "memory")
#define B_READY 9
#define B_FREE  10
#define B_CONS  11

#define LDSM_X4(R0,R1,R2,R3,ADDR) \
    asm volatile("ldmatrix.sync.aligned.m8n8.x4.shared.b16 {%0,%1,%2,%3}, [%4];" \
                 : "=r"(R0), "=r"(R1), "=r"(R2), "=r"(R3) : "r"(ADDR))

#define MMA_16816(D_, A0,A1,A2,A3, B0,B1) \
    asm volatile("mma.sync.aligned.m16n8k16.row.col.f32.f16.f16.f32 " \
                 "{%0,%1,%2,%3}, {%4,%5,%6,%7}, {%8,%9}, {%0,%1,%2,%3};" \
                 : "+f"((D_)[0]), "+f"((D_)[1]), "+f"((D_)[2]), "+f"((D_)[3]) \
                 : "r"(A0), "r"(A1), "r"(A2), "r"(A3), "r"(B0), "r"(B1))

__device__ __forceinline__ uint32_t pack_relu2(float x, float y) {
    __half2 h = __floats2half2_rn(fmaxf(x, 0.f), fmaxf(y, 0.f));
    return *(uint32_t*)&h;
}

// ---- prep kernels ----
__global__ void pack_weights(const float* __restrict__ W1,
                             const float* __restrict__ W2,
                             const float* __restrict__ W3) {
    int i = blockIdx.x * 256 + threadIdx.x;      // 68*256 = 17408
    if (i < 128 * 136) {
        int n = i / 136, c = i % 136;
        g_W2h[i] = __float2half((c < 128) ? W2[n * 128 + c] : 0.f);
        g_W3h[i] = __float2half((c < 128) ? W3[n * 128 + c] : 0.f);
    }
    if (i < 128 * 24) {
        int n = i / 24, c = i % 24;
        g_W1h[i] = __float2half((c < 15) ? W1[n * 15 + c] : 0.f);
    }
}

__global__ void precompute_MT(const float* __restrict__ Uq, const float* __restrict__ Ur) {
    int j = blockIdx.x, t = threadIdx.x;
    float acc = 0.f;
    #pragma unroll 8
    for (int k = 0; k < 128; ++k)
        acc += Ur[k * 128 + t] * Uq[k * 128 + j];
    g_MT[j * 128 + t] = acc;
}

extern __shared__ char smem[];

__global__ __launch_bounds__(kThreads, 1) void fused_attn_hmma(
    const float* __restrict__ obs,
    const float* __restrict__ b1, const float* __restrict__ b2, const float* __restrict__ b3,
    float* __restrict__ out)
{
    const uint32_t sb = smem_u32(smem);
    const int tid = threadIdx.x;

    // stage weights + biases (all 384 threads)
    {
        const uint4* s1 = (const uint4*)g_W1h;
        const uint4* s2 = (const uint4*)g_W2h;
        const uint4* s3 = (const uint4*)g_W3h;
        for (int i = tid; i < 384;  i += kThreads) *(uint4*)(smem + OFF_W1T + i * 16) = s1[i];
        for (int i = tid; i < 2176; i += kThreads) *(uint4*)(smem + OFF_W2T + i * 16) = s2[i];
        for (int i = tid; i < 2176; i += kThreads) *(uint4*)(smem + OFF_W3T + i * 16) = s3[i];
        if (tid < 128) {
            ((float*)(smem + OFF_BIAS))[tid]       = b1[tid];
            ((float*)(smem + OFF_BIAS))[128 + tid] = b2[tid];
            ((float*)(smem + OFF_BIAS))[256 + tid] = b3[tid];
        }
    }
    __syncthreads();

    float* fs      = (float*)(smem + OFF_FS);
    float* xr      = (float*)(smem + OFF_XR);
    const float* bias = (const float*)(smem + OFF_BIAS);
    float* msp_db  = (float*)(smem + OFF_MSPDB);    // [2][8]
    float* mask_db = (float*)(smem + OFF_MASKDB);   // [2][128]

    if (tid < kProd) {
        // =================== PRODUCER (256 threads, 8 warps) ===================
        const int lane = tid & 31;
        const int s    = tid >> 5;                // strip 0..7, rows 16s..16s+15
        const int r0   = s * 16;

        const uint32_t aAddr = sb + OFF_A + (uint32_t)(r0 + (lane & 15)) * W1_STRIDE + (uint32_t)(lane >> 4) * 16;
        const uint32_t brow  = (uint32_t)((lane & 7) + ((lane >> 4) << 3));
        const uint32_t koff  = (uint32_t)(((lane >> 3) & 1) * 16);
        const uint32_t bW1   = sb + OFF_W1T + brow * W1_STRIDE + koff;
        const uint32_t bW2   = sb + OFF_W2T + brow * W_STRIDE + koff;
        const uint32_t bW3   = sb + OFF_W3T + brow * W_STRIDE + koff;

        const int rA = r0 + (lane >> 2);          // rows rA and rA+8
        const int cn = (lane & 3) * 2;            // col offset within n-tile

        // fs staging: warp-local 16 rows x 4 float4; lane handles i = lane, lane+32
        const int fr0 = r0 + (lane >> 2), fc0 = lane & 3;          // i = lane
        const int fr1 = r0 + 8 + (lane >> 2), fc1 = lane & 3;      // i = lane+32

        float4 pf0, pf1;
        {
            const float4* o4 = (const float4*)(obs + (size_t)blockIdx.x * 4 * 576);
            pf0 = o4[(fr0 >> 5) * 144 + 8 + (fr0 & 31) * 4 + fc0];
            pf1 = o4[(fr1 >> 5) * 144 + 8 + (fr1 & 31) * 4 + fc1];
        }

        int buf = 0;
        for (int tile = blockIdx.x; tile < kTiles; tile += kGrid, buf ^= 1) {
            // ---- commit prefetched att (warp-local rows) ----
            ((float4*)fs)[fr0 * 4 + fc0] = pf0;
            ((float4*)fs)[fr1 * 4 + fc1] = pf1;
            __syncwarp();

            // ---- A1: feats fp16 (warp rows) + mask/msum ----
            #pragma unroll
            for (int k2 = 0; k2 < 4; ++k2) {
                const int i = lane + 32 * k2;
                const int r = r0 + (i >> 3), cp = i & 7;
                float2 v = *(const float2*)(fs + r * 16 + 2 * cp);
                if (cp == 7) v.y = 0.f;           // col 15 = mask -> 0
                __half2 h = __floats2half2_rn(v.x, v.y);
                *(uint32_t*)(smem + OFF_A + r * W1_STRIDE + cp * 4) = *(uint32_t*)&h;
            }
            if (lane < 16)
                mask_db[buf * 128 + r0 + lane] = fs[(r0 + lane) * 16 + 15];
            if (lane == 0) {
                float ssum = 0.f;
                #pragma unroll
                for (int rr = 0; rr < 16; ++rr) ssum += fs[(r0 + rr) * 16 + 15];
                msp_db[buf * 8 + s] = ssum;
            }
            __syncwarp();

            float d[16][4];
            uint32_t af0[8], af1[8], af2[8], af3[8];

            // ---- layer 1 (K=16): A from smem, all 128 N-cols ----
            #pragma unroll
            for (int nt = 0; nt < 16; ++nt)
                { d[nt][0] = d[nt][1] = d[nt][2] = d[nt][3] = 0.f; }
            {
                uint32_t a0, a1, a2, a3;
                LDSM_X4(a0, a1, a2, a3, aAddr);
                #pragma unroll
                for (int nt2 = 0; nt2 < 8; ++nt2) {
                    uint32_t q0, q1, q2, q3;
                    LDSM_X4(q0, q1, q2, q3, bW1 + nt2 * 16 * W1_STRIDE);
                    MMA_16816(d[2 * nt2],     a0, a1, a2, a3, q0, q1);
                    MMA_16816(d[2 * nt2 + 1], a0, a1, a2, a3, q2, q3);
                }
            }
            // epi1: relu(+b1) -> A fragments (registers; D-layout == A-layout)
            #pragma unroll
            for (int kt = 0; kt < 8; ++kt) {
                const int n0 = kt * 16 + cn, n1 = kt * 16 + 8 + cn;
                af0[kt] = pack_relu2(d[2 * kt][0] + bias[n0], d[2 * kt][1] + bias[n0 + 1]);
                af1[kt] = pack_relu2(d[2 * kt][2] + bias[n0], d[2 * kt][3] + bias[n0 + 1]);
                af2[kt] = pack_relu2(d[2 * kt + 1][0] + bias[n1], d[2 * kt + 1][1] + bias[n1 + 1]);
                af3[kt] = pack_relu2(d[2 * kt + 1][2] + bias[n1], d[2 * kt + 1][3] + bias[n1 + 1]);
            }

            // ---- layer 2 (K=128): A from registers ----
            #pragma unroll
            for (int nt = 0; nt < 16; ++nt)
                { d[nt][0] = d[nt][1] = d[nt][2] = d[nt][3] = 0.f; }
            #pragma unroll
            for (int kt = 0; kt < 8; ++kt) {
                #pragma unroll
                for (int nt2 = 0; nt2 < 8; ++nt2) {
                    uint32_t q0, q1, q2, q3;
                    LDSM_X4(q0, q1, q2, q3, bW2 + nt2 * 16 * W_STRIDE + kt * 32);
                    MMA_16816(d[2 * nt2],     af0[kt], af1[kt], af2[kt], af3[kt], q0, q1);
                    MMA_16816(d[2 * nt2 + 1], af0[kt], af1[kt], af2[kt], af3[kt], q2, q3);
                }
            }
            #pragma unroll
            for (int kt = 0; kt < 8; ++kt) {      // epi2: relu(+b2) -> fragments
                const int n0 = kt * 16 + cn, n1 = kt * 16 + 8 + cn;
                af0[kt] = pack_relu2(d[2 * kt][0] + bias[128 + n0], d[2 * kt][1] + bias[128 + n0 + 1]);
                af1[kt] = pack_relu2(d[2 * kt][2] + bias[128 + n0], d[2 * kt][3] + bias[128 + n0 + 1]);
                af2[kt] = pack_relu2(d[2 * kt + 1][0] + bias[128 + n1], d[2 * kt + 1][1] + bias[128 + n1 + 1]);
                af3[kt] = pack_relu2(d[2 * kt + 1][2] + bias[128 + n1], d[2 * kt + 1][3] + bias[128 + n1 + 1]);
            }

            // ---- layer 3 (K=128): A from registers ----
            #pragma unroll
            for (int nt = 0; nt < 16; ++nt)
                { d[nt][0] = d[nt][1] = d[nt][2] = d[nt][3] = 0.f; }
            #pragma unroll
            for (int kt = 0; kt < 8; ++kt) {
                #pragma unroll
                for (int nt2 = 0; nt2 < 8; ++nt2) {
                    uint32_t q0, q1, q2, q3;
                    LDSM_X4(q0, q1, q2, q3, bW3 + nt2 * 16 * W_STRIDE + kt * 32);
                    MMA_16816(d[2 * nt2],     af0[kt], af1[kt], af2[kt], af3[kt], q0, q1);
                    MMA_16816(d[2 * nt2 + 1], af0[kt], af1[kt], af2[kt], af3[kt], q2, q3);
                }
            }

            // masks into registers before any cross-phase barrier
            const float mkA = fs[rA * 16 + 15];
            const float mkB = fs[(rA + 8) * 16 + 15];

            // ---- prefetch next tile's obs (before blocking on consumer) ----
            {
                const int ntile = tile + kGrid;
                if (ntile < kTiles) {
                    const float4* o4 = (const float4*)(obs + (size_t)ntile * 4 * 576);
                    pf0 = o4[(fr0 >> 5) * 144 + 8 + (fr0 & 31) * 4 + fc0];
                    pf1 = o4[(fr1 >> 5) * 144 + 8 + (fr1 & 31) * 4 + fc1];
                }
            }

            // ---- wait for consumer to release xr, then store xr ----
            BAR_SYNC(B_FREE, kThreads);
            #pragma unroll
            for (int nt = 0; nt < 16; ++nt) {
                const int n = nt * 8 + cn;
                float2 xA = make_float2((d[nt][0] + bias[256 + n]) * mkA,
                                        (d[nt][1] + bias[256 + n + 1]) * mkA);
                float2 xB = make_float2((d[nt][2] + bias[256 + n]) * mkB,
                                        (d[nt][3] + bias[256 + n + 1]) * mkB);
                *(float2*)(xr + rA * 130 + n)       = xA;
                *(float2*)(xr + (rA + 8) * 130 + n) = xB;
            }
            BAR_ARRIVE(B_READY, kThreads);
        }
    } else {
        // =================== CONSUMER (128 threads, 4 warps) ===================
        const int tid2 = tid - kProd;             // 0..127
        const int cw   = tid2 >> 5;               // consumer warp 0..3 = batch row
        float* q_cs = (float*)(smem + OFF_QCS);
        float* p_cs = (float*)(smem + OFF_PCS);
        float* w_cs = (float*)(smem + OFF_WCS);

        BAR_ARRIVE(B_FREE, kThreads);             // prime the pipeline

        int buf = 0;
        for (int tile = blockIdx.x; tile < kTiles; tile += kGrid, buf ^= 1) {
            const int b0 = tile * 4;

            // aux passthrough (overlaps producer GEMM; independent of xr)
            if (tid2 < 64) {
                const float4* o4 = (const float4*)(obs + (size_t)b0 * 576);
                const int lb = tid2 >> 4, j = tid2 & 15;
                float4 v = (j < 8) ? o4[lb * 144 + j] : o4[lb * 144 + 136 + (j - 8)];
                ((float4*)(out + (size_t)b0 * 192))[lb * 48 + j] = v;
            }

            BAR_SYNC(B_READY, kThreads);          // xr, msp, mask ready

            const int dd = tid2;                  // 0..127 (feature dim)
            // ---- query from xr ----
            #pragma unroll
            for (int lb = 0; lb < 4; ++lb) {
                float qs = 0.f;
                #pragma unroll 8
                for (int o = 0; o < 32; ++o)
                    qs += xr[(lb * 32 + o) * 130 + dd];
                q_cs[lb * 128 + dd] = qs / (msp_db[buf * 8 + 2 * lb] + msp_db[buf * 8 + 2 * lb + 1] + 1e-5f);
            }
            BAR_SYNC(B_CONS, 128);

            // ---- p = MT q (g_MT hot in L2) ----
            {
                float p0 = 0.f, p1 = 0.f, p2 = 0.f, p3 = 0.f;
                #pragma unroll 8
                for (int j = 0; j < 128; ++j) {
                    const float m = g_MT[j * 128 + dd];
                    p0 += m * q_cs[j];
                    p1 += m * q_cs[128 + j];
                    p2 += m * q_cs[256 + j];
                    p3 += m * q_cs[384 + j];
                }
                p_cs[dd]       = p0;
                p_cs[128 + dd] = p1;
                p_cs[256 + dd] = p2;
                p_cs[384 + dd] = p3;
            }
            BAR_SYNC(B_CONS, 128);

            // ---- logits + softmax: warp cw owns batch row cw, lane = object ----
            {
                const int row = tid2;             // object row 0..127, batch = row>>5 = cw
                float ls = 0.f;
                #pragma unroll 8
                for (int k = 0; k < 128; ++k)
                    ls += p_cs[cw * 128 + k] * xr[row * 130 + k];
                ls += (1.f - mask_db[buf * 128 + row]) * -1e9f;
                float mx = ls;
                #pragma unroll
                for (int sh = 16; sh > 0; sh >>= 1) mx = fmaxf(mx, __shfl_xor_sync(0xffffffffu, mx, sh));
                const float e = __expf(ls - mx);
                float ssum = e;
                #pragma unroll
                for (int sh = 16; sh > 0; sh >>= 1) ssum += __shfl_xor_sync(0xffffffffu, ssum, sh);
                w_cs[row] = e / ssum;
            }
            BAR_SYNC(B_CONS, 128);

            // ---- out_att ----
            #pragma unroll
            for (int lb = 0; lb < 4; ++lb) {
                float acc = 0.f;
                #pragma unroll 8
                for (int o = 0; o < 32; ++o)
                    acc += w_cs[lb * 32 + o] * xr[(lb * 32 + o) * 130 + dd];
                out[(size_t)(b0 + lb) * 192 + 64 + dd] = acc;
            }

            BAR_ARRIVE(B_FREE, kThreads);         // release xr for next tile
        }
    }
}

extern "C" void kernel_launch(void* const* d_in, const int* in_sizes, int n_in,
                              void* d_out, int out_size) {
    const float* obs = (const float*)d_in[0];
    const float* W1  = (const float*)d_in[1];
    const float* b1  = (const float*)d_in[2];
    const float* W2  = (const float*)d_in[3];
    const float* b2  = (const float*)d_in[4];
    const float* W3  = (const float*)d_in[5];
    const float* b3  = (const float*)d_in[6];
    const float* Uq  = (const float*)d_in[7];
    const float* Ur  = (const float*)d_in[8];
    float* out = (float*)d_out;

    cudaFuncSetAttribute(fused_attn_hmma,
                         cudaFuncAttributeMaxDynamicSharedMemorySize, (int)SMEM_BYTES);

    pack_weights<<<68, 256>>>(W1, W2, W3);
    precompute_MT<<<128, 128>>>(Uq, Ur);
    fused_attn_hmma<<<kGrid, kThreads, SMEM_BYTES>>>(obs, b1, b2, b3, out);
}

// round 15
// speedup vs baseline: 1.1334x; 1.0127x over previous
#include <cuda_runtime.h>
#include <cuda_fp16.h>
#include <cstdint>

// ---------------------------------------------------------------------------
// BaseAttention fused — HMMA m16n8k16, register-resident layer chaining,
// xr DOUBLE-BUFFERED pipeline with PER-BUFFER free barriers (deadlock-safe:
// one outstanding bar.arrive per barrier).
//   8 producer warps: warp s owns rows [16s,16s+16) x all 128 cols.
//   4 consumer warps: attention tail of the previous tile.
// B_READY(9): producer arrives per tile / consumer syncs.
// B_FREE0(10)/B_FREE1(11): consumer pre-arms once each, re-arms after
// finishing buf b; producer syncs buf b's barrier before storing xr[b].
// ---------------------------------------------------------------------------

#define kBatch   32768
#define kTiles   (kBatch / 4)     // 8192
#define kGrid    148
#define kProd    256
#define kThreads 384

// smem byte offsets
#define OFF_FS      0                // [128][16] f32 raw att (producer-private) 8192
#define OFF_BIAS    8192             // b1,b2,b3 f32                             1536
#define OFF_MSPDB   9728             // [2][8] f32 strip mask sums                 64
#define OFF_MASKDB  9792             // [2][128] f32 masks                       1024
#define OFF_QCS     10816            // [4][128] f32 consumer query              2048
#define OFF_PCS     12864            // [4][128] f32 consumer p                  2048
#define OFF_WCS     14912            // [128] f32 softmax w                       512
#define OFF_W1T     15424            // [128][24] f16 (k-pad 15->16)             6144
#define OFF_A       21568            // [128][24] f16 A1 tile (stride 48B)       6144
#define OFF_W2T     27712            // [128][136] f16                          34816
#define OFF_W3T     62528            // [128][136] f16                          34816
#define OFF_XR      97344            // [2][128][130] f32 double buffer       2x66560
#define XR_STRIDE_F 16640            // floats per xr buffer
#define SMEM_BYTES  230464           // <= 232448 opt-in limit

#define W_STRIDE  272                // bytes per W2/W3 row (136 halves)
#define W1_STRIDE 48                 // bytes per W1/A1 row (24 halves)

__device__ __half g_W1h[128 * 24];
__device__ __half g_W2h[128 * 136];
__device__ __half g_W3h[128 * 136];
__device__ float  g_MT[128 * 128];   // MT[j*128+t] = sum_k Ur[k,t]*Uq[k,j]

__device__ __forceinline__ uint32_t smem_u32(const void* p) {
    uint32_t a;
    asm("{ .reg .u64 t; cvta.to.shared.u64 t, %1; cvt.u32.u64 %0, t; }" : "=r"(a) : "l"(p));
    return a;
}

#define BAR_SYNC(ID,N)   asm volatile("bar.sync %0, %1;"   :: "r"(ID), "r"(N) : "memory")
#define BAR_ARRIVE(ID,N) asm volatile("bar.arrive %0, %1;" :: "r"(ID), "r"(N) : "memory")
#define B_READY 9
#define B_FREE0 10
#define B_FREE1 11
#define B_CONS  12

#define LDSM_X4(R0,R1,R2,R3,ADDR) \
    asm volatile("ldmatrix.sync.aligned.m8n8.x4.shared.b16 {%0,%1,%2,%3}, [%4];" \
                 : "=r"(R0), "=r"(R1), "=r"(R2), "=r"(R3) : "r"(ADDR))

#define MMA_16816(D_, A0,A1,A2,A3, B0,B1) \
    asm volatile("mma.sync.aligned.m16n8k16.row.col.f32.f16.f16.f32 " \
                 "{%0,%1,%2,%3}, {%4,%5,%6,%7}, {%8,%9}, {%0,%1,%2,%3};" \
                 : "+f"((D_)[0]), "+f"((D_)[1]), "+f"((D_)[2]), "+f"((D_)[3]) \
                 : "r"(A0), "r"(A1), "r"(A2), "r"(A3), "r"(B0), "r"(B1))

__device__ __forceinline__ uint32_t pack_relu2(float x, float y) {
    __half2 h = __floats2half2_rn(fmaxf(x, 0.f), fmaxf(y, 0.f));
    return *(uint32_t*)&h;
}

// ---- prep kernels ----
__global__ void pack_weights(const float* __restrict__ W1,
                             const float* __restrict__ W2,
                             const float* __restrict__ W3) {
    int i = blockIdx.x * 256 + threadIdx.x;      // 68*256 = 17408
    if (i < 128 * 136) {
        int n = i / 136, c = i % 136;
        g_W2h[i] = __float2half((c < 128) ? W2[n * 128 + c] : 0.f);
        g_W3h[i] = __float2half((c < 128) ? W3[n * 128 + c] : 0.f);
    }
    if (i < 128 * 24) {
        int n = i / 24, c = i % 24;
        g_W1h[i] = __float2half((c < 15) ? W1[n * 15 + c] : 0.f);
    }
}

__global__ void precompute_MT(const float* __restrict__ Uq, const float* __restrict__ Ur) {
    int j = blockIdx.x, t = threadIdx.x;
    float acc = 0.f;
    #pragma unroll 8
    for (int k = 0; k < 128; ++k)
        acc += Ur[k * 128 + t] * Uq[k * 128 + j];
    g_MT[j * 128 + t] = acc;
}

extern __shared__ char smem[];

__global__ __launch_bounds__(kThreads, 1) void fused_attn_hmma(
    const float* __restrict__ obs,
    const float* __restrict__ b1, const float* __restrict__ b2, const float* __restrict__ b3,
    float* __restrict__ out)
{
    const uint32_t sb = smem_u32(smem);
    const int tid = threadIdx.x;

    // stage weights + biases (all 384 threads)
    {
        const uint4* s1 = (const uint4*)g_W1h;
        const uint4* s2 = (const uint4*)g_W2h;
        const uint4* s3 = (const uint4*)g_W3h;
        for (int i = tid; i < 384;  i += kThreads) *(uint4*)(smem + OFF_W1T + i * 16) = s1[i];
        for (int i = tid; i < 2176; i += kThreads) *(uint4*)(smem + OFF_W2T + i * 16) = s2[i];
        for (int i = tid; i < 2176; i += kThreads) *(uint4*)(smem + OFF_W3T + i * 16) = s3[i];
        if (tid < 128) {
            ((float*)(smem + OFF_BIAS))[tid]       = b1[tid];
            ((float*)(smem + OFF_BIAS))[128 + tid] = b2[tid];
            ((float*)(smem + OFF_BIAS))[256 + tid] = b3[tid];
        }
    }
    __syncthreads();

    float* fs      = (float*)(smem + OFF_FS);
    float* xr0     = (float*)(smem + OFF_XR);
    const float* bias = (const float*)(smem + OFF_BIAS);
    float* msp_db  = (float*)(smem + OFF_MSPDB);    // [2][8]
    float* mask_db = (float*)(smem + OFF_MASKDB);   // [2][128]

    if (tid < kProd) {
        // =================== PRODUCER (256 threads, 8 warps) ===================
        const int lane = tid & 31;
        const int s    = tid >> 5;                // strip 0..7, rows 16s..16s+15
        const int r0   = s * 16;

        const uint32_t aAddr = sb + OFF_A + (uint32_t)(r0 + (lane & 15)) * W1_STRIDE + (uint32_t)(lane >> 4) * 16;
        const uint32_t brow  = (uint32_t)((lane & 7) + ((lane >> 4) << 3));
        const uint32_t koff  = (uint32_t)(((lane >> 3) & 1) * 16);
        const uint32_t bW1   = sb + OFF_W1T + brow * W1_STRIDE + koff;
        const uint32_t bW2   = sb + OFF_W2T + brow * W_STRIDE + koff;
        const uint32_t bW3   = sb + OFF_W3T + brow * W_STRIDE + koff;

        const int rA = r0 + (lane >> 2);          // rows rA and rA+8
        const int cn = (lane & 3) * 2;            // col offset within n-tile

        // fs staging: warp-local 16 rows x 4 float4
        const int fr0 = r0 + (lane >> 2), fc0 = lane & 3;          // i = lane
        const int fr1 = r0 + 8 + (lane >> 2), fc1 = lane & 3;      // i = lane+32

        float4 pf0, pf1;
        {
            const float4* o4 = (const float4*)(obs + (size_t)blockIdx.x * 4 * 576);
            pf0 = o4[(fr0 >> 5) * 144 + 8 + (fr0 & 31) * 4 + fc0];
            pf1 = o4[(fr1 >> 5) * 144 + 8 + (fr1 & 31) * 4 + fc1];
        }

        int buf = 0;
        for (int tile = blockIdx.x; tile < kTiles; tile += kGrid, buf ^= 1) {
            // ---- commit prefetched att (warp-local rows) ----
            ((float4*)fs)[fr0 * 4 + fc0] = pf0;
            ((float4*)fs)[fr1 * 4 + fc1] = pf1;
            __syncwarp();

            // ---- A1: feats fp16 (warp rows) ----
            #pragma unroll
            for (int k2 = 0; k2 < 4; ++k2) {
                const int i = lane + 32 * k2;
                const int r = r0 + (i >> 3), cp = i & 7;
                float2 v = *(const float2*)(fs + r * 16 + 2 * cp);
                if (cp == 7) v.y = 0.f;           // col 15 = mask -> 0
                __half2 h = __floats2half2_rn(v.x, v.y);
                *(uint32_t*)(smem + OFF_A + r * W1_STRIDE + cp * 4) = *(uint32_t*)&h;
            }
            __syncwarp();

            float d[16][4];
            uint32_t af0[8], af1[8], af2[8], af3[8];

            // ---- layer 1 (K=16): A from smem, all 128 N-cols ----
            #pragma unroll
            for (int nt = 0; nt < 16; ++nt)
                { d[nt][0] = d[nt][1] = d[nt][2] = d[nt][3] = 0.f; }
            {
                uint32_t a0, a1, a2, a3;
                LDSM_X4(a0, a1, a2, a3, aAddr);
                #pragma unroll
                for (int nt2 = 0; nt2 < 8; ++nt2) {
                    uint32_t q0, q1, q2, q3;
                    LDSM_X4(q0, q1, q2, q3, bW1 + nt2 * 16 * W1_STRIDE);
                    MMA_16816(d[2 * nt2],     a0, a1, a2, a3, q0, q1);
                    MMA_16816(d[2 * nt2 + 1], a0, a1, a2, a3, q2, q3);
                }
            }
            #pragma unroll
            for (int kt = 0; kt < 8; ++kt) {      // epi1: relu(+b1) -> fragments
                const int n0 = kt * 16 + cn, n1 = kt * 16 + 8 + cn;
                af0[kt] = pack_relu2(d[2 * kt][0] + bias[n0], d[2 * kt][1] + bias[n0 + 1]);
                af1[kt] = pack_relu2(d[2 * kt][2] + bias[n0], d[2 * kt][3] + bias[n0 + 1]);
                af2[kt] = pack_relu2(d[2 * kt + 1][0] + bias[n1], d[2 * kt + 1][1] + bias[n1 + 1]);
                af3[kt] = pack_relu2(d[2 * kt + 1][2] + bias[n1], d[2 * kt + 1][3] + bias[n1 + 1]);
            }

            // ---- layer 2 (K=128): A from registers ----
            #pragma unroll
            for (int nt = 0; nt < 16; ++nt)
                { d[nt][0] = d[nt][1] = d[nt][2] = d[nt][3] = 0.f; }
            #pragma unroll
            for (int kt = 0; kt < 8; ++kt) {
                #pragma unroll
                for (int nt2 = 0; nt2 < 8; ++nt2) {
                    uint32_t q0, q1, q2, q3;
                    LDSM_X4(q0, q1, q2, q3, bW2 + nt2 * 16 * W_STRIDE + kt * 32);
                    MMA_16816(d[2 * nt2],     af0[kt], af1[kt], af2[kt], af3[kt], q0, q1);
                    MMA_16816(d[2 * nt2 + 1], af0[kt], af1[kt], af2[kt], af3[kt], q2, q3);
                }
            }
            #pragma unroll
            for (int kt = 0; kt < 8; ++kt) {      // epi2: relu(+b2) -> fragments
                const int n0 = kt * 16 + cn, n1 = kt * 16 + 8 + cn;
                af0[kt] = pack_relu2(d[2 * kt][0] + bias[128 + n0], d[2 * kt][1] + bias[128 + n0 + 1]);
                af1[kt] = pack_relu2(d[2 * kt][2] + bias[128 + n0], d[2 * kt][3] + bias[128 + n0 + 1]);
                af2[kt] = pack_relu2(d[2 * kt + 1][0] + bias[128 + n1], d[2 * kt + 1][1] + bias[128 + n1 + 1]);
                af3[kt] = pack_relu2(d[2 * kt + 1][2] + bias[128 + n1], d[2 * kt + 1][3] + bias[128 + n1 + 1]);
            }

            // masks + next-tile prefetch BEFORE layer 3 (GEMM hides GMEM latency)
            const float mkA = fs[rA * 16 + 15];
            const float mkB = fs[(rA + 8) * 16 + 15];
            {
                const int ntile = tile + kGrid;
                if (ntile < kTiles) {
                    const float4* o4 = (const float4*)(obs + (size_t)ntile * 4 * 576);
                    pf0 = o4[(fr0 >> 5) * 144 + 8 + (fr0 & 31) * 4 + fc0];
                    pf1 = o4[(fr1 >> 5) * 144 + 8 + (fr1 & 31) * 4 + fc1];
                }
            }

            // ---- layer 3 (K=128): A from registers ----
            #pragma unroll
            for (int nt = 0; nt < 16; ++nt)
                { d[nt][0] = d[nt][1] = d[nt][2] = d[nt][3] = 0.f; }
            #pragma unroll
            for (int kt = 0; kt < 8; ++kt) {
                #pragma unroll
                for (int nt2 = 0; nt2 < 8; ++nt2) {
                    uint32_t q0, q1, q2, q3;
                    LDSM_X4(q0, q1, q2, q3, bW3 + nt2 * 16 * W_STRIDE + kt * 32);
                    MMA_16816(d[2 * nt2],     af0[kt], af1[kt], af2[kt], af3[kt], q0, q1);
                    MMA_16816(d[2 * nt2 + 1], af0[kt], af1[kt], af2[kt], af3[kt], q2, q3);
                }
            }

            // ---- wait for THIS buffer to be free (non-blocking in steady state) ----
            if (buf == 0) BAR_SYNC(B_FREE0, kThreads);
            else          BAR_SYNC(B_FREE1, kThreads);
            {
                float* xrb = xr0 + buf * XR_STRIDE_F;
                #pragma unroll
                for (int nt = 0; nt < 16; ++nt) {
                    const int n = nt * 8 + cn;
                    float2 xA = make_float2((d[nt][0] + bias[256 + n]) * mkA,
                                            (d[nt][1] + bias[256 + n + 1]) * mkA);
                    float2 xB = make_float2((d[nt][2] + bias[256 + n]) * mkB,
                                            (d[nt][3] + bias[256 + n + 1]) * mkB);
                    *(float2*)(xrb + rA * 130 + n)       = xA;
                    *(float2*)(xrb + (rA + 8) * 130 + n) = xB;
                }
            }
            // mask / msum stores (after the free-sync: same lifetime as xr[buf])
            if (lane < 16)
                mask_db[buf * 128 + r0 + lane] = fs[(r0 + lane) * 16 + 15];
            if (lane == 0) {
                float ssum = 0.f;
                #pragma unroll
                for (int rr = 0; rr < 16; ++rr) ssum += fs[(r0 + rr) * 16 + 15];
                msp_db[buf * 8 + s] = ssum;
            }
            BAR_ARRIVE(B_READY, kThreads);
        }
    } else {
        // =================== CONSUMER (128 threads, 4 warps) ===================
        const int tid2 = tid - kProd;             // 0..127
        const int cw   = tid2 >> 5;               // consumer warp 0..3 = batch row
        float* q_cs = (float*)(smem + OFF_QCS);
        float* p_cs = (float*)(smem + OFF_PCS);
        float* w_cs = (float*)(smem + OFF_WCS);

        BAR_ARRIVE(B_FREE0, kThreads);            // pre-arm buf 0 (1 outstanding)
        BAR_ARRIVE(B_FREE1, kThreads);            // pre-arm buf 1 (1 outstanding)

        int buf = 0;
        for (int tile = blockIdx.x; tile < kTiles; tile += kGrid, buf ^= 1) {
            const int b0 = tile * 4;
            const float* xrb = xr0 + buf * XR_STRIDE_F;

            // aux passthrough (overlaps producer GEMM; independent of xr)
            if (tid2 < 64) {
                const float4* o4 = (const float4*)(obs + (size_t)b0 * 576);
                const int lb = tid2 >> 4, j = tid2 & 15;
                float4 v = (j < 8) ? o4[lb * 144 + j] : o4[lb * 144 + 136 + (j - 8)];
                ((float4*)(out + (size_t)b0 * 192))[lb * 48 + j] = v;
            }

            BAR_SYNC(B_READY, kThreads);          // xr[buf], msp, mask ready

            const int dd = tid2;                  // 0..127 (feature dim)
            // ---- query from xr ----
            #pragma unroll
            for (int lb = 0; lb < 4; ++lb) {
                float qs = 0.f;
                #pragma unroll 8
                for (int o = 0; o < 32; ++o)
                    qs += xrb[(lb * 32 + o) * 130 + dd];
                q_cs[lb * 128 + dd] = qs / (msp_db[buf * 8 + 2 * lb] + msp_db[buf * 8 + 2 * lb + 1] + 1e-5f);
            }
            BAR_SYNC(B_CONS, 128);

            // ---- p = MT q (g_MT hot in L2) ----
            {
                float p0 = 0.f, p1 = 0.f, p2 = 0.f, p3 = 0.f;
                #pragma unroll 8
                for (int j = 0; j < 128; ++j) {
                    const float m = g_MT[j * 128 + dd];
                    p0 += m * q_cs[j];
                    p1 += m * q_cs[128 + j];
                    p2 += m * q_cs[256 + j];
                    p3 += m * q_cs[384 + j];
                }
                p_cs[dd]       = p0;
                p_cs[128 + dd] = p1;
                p_cs[256 + dd] = p2;
                p_cs[384 + dd] = p3;
            }
            BAR_SYNC(B_CONS, 128);

            // ---- logits + softmax: warp cw owns batch row cw, lane = object ----
            {
                const int row = tid2;             // object row 0..127, batch = row>>5 = cw
                float ls = 0.f;
                #pragma unroll 8
                for (int k = 0; k < 128; ++k)
                    ls += p_cs[cw * 128 + k] * xrb[row * 130 + k];
                ls += (1.f - mask_db[buf * 128 + row]) * -1e9f;
                float mx = ls;
                #pragma unroll
                for (int sh = 16; sh > 0; sh >>= 1) mx = fmaxf(mx, __shfl_xor_sync(0xffffffffu, mx, sh));
                const float e = __expf(ls - mx);
                float ssum = e;
                #pragma unroll
                for (int sh = 16; sh > 0; sh >>= 1) ssum += __shfl_xor_sync(0xffffffffu, ssum, sh);
                w_cs[row] = e / ssum;
            }
            BAR_SYNC(B_CONS, 128);

            // ---- out_att ----
            #pragma unroll
            for (int lb = 0; lb < 4; ++lb) {
                float acc = 0.f;
                #pragma unroll 8
                for (int o = 0; o < 32; ++o)
                    acc += w_cs[lb * 32 + o] * xrb[(lb * 32 + o) * 130 + dd];
                out[(size_t)(b0 + lb) * 192 + 64 + dd] = acc;
            }

            // release THIS buffer for the producer's t+2 iteration
            if (buf == 0) BAR_ARRIVE(B_FREE0, kThreads);
            else          BAR_ARRIVE(B_FREE1, kThreads);
        }
    }
}

extern "C" void kernel_launch(void* const* d_in, const int* in_sizes, int n_in,
                              void* d_out, int out_size) {
    const float* obs = (const float*)d_in[0];
    const float* W1  = (const float*)d_in[1];
    const float* b1  = (const float*)d_in[2];
    const float* W2  = (const float*)d_in[3];
    const float* b2  = (const float*)d_in[4];
    const float* W3  = (const float*)d_in[5];
    const float* b3  = (const float*)d_in[6];
    const float* Uq  = (const float*)d_in[7];
    const float* Ur  = (const float*)d_in[8];
    float* out = (float*)d_out;

    cudaFuncSetAttribute(fused_attn_hmma,
                         cudaFuncAttributeMaxDynamicSharedMemorySize, (int)SMEM_BYTES);

    pack_weights<<<68, 256>>>(W1, W2, W3);
    precompute_MT<<<128, 128>>>(Uq, Ur);
    fused_attn_hmma<<<kGrid, kThreads, SMEM_BYTES>>>(obs, b1, b2, b3, out);
}